// round 5
// baseline (speedup 1.0000x reference)
#include <cuda_runtime.h>
#include <math_constants.h>

// Shapes (fixed): x: [B=32, C=256, H=128, W=128] float32
#define B_   32
#define C_   256
#define HW_  16384   // 128*128
#define HW4_ 4096    // HW/4 (float4 groups)

#define XN_BLOCKS 128    // K2: one block per 32-float4 spatial slice
#define HIST_BLOCKS 64

// Scratch (device globals — no allocation allowed)
__device__ float g_pooled[B_ * C_];      // 32 KB
__device__ float g_ssum[XN_BLOCKS];      // sigmoid partial per block
__device__ float g_entro[HW_];           // 64 KB
__device__ float g_mm[XN_BLOCKS * 2];    // per-block (min,max)
__device__ int   g_hist[256];
__device__ int   g_cnt;                  // last-block counter

// ---------------------------------------------------------------------------
// K1: pooled[b,c] = mean over HW. One block per (b,c). Block 0 zeroes the
//     histogram + counter for this graph replay.
// ---------------------------------------------------------------------------
__global__ void __launch_bounds__(256) k_pool(const float* __restrict__ x) {
    if (blockIdx.x == 0) {
        g_hist[threadIdx.x] = 0;
        if (threadIdx.x == 0) g_cnt = 0;
    }

    const int bc = blockIdx.x;   // 0..8191
    const float4* __restrict__ p = reinterpret_cast<const float4*>(x) + (size_t)bc * HW4_;

    float s = 0.0f;
#pragma unroll
    for (int i = 0; i < 16; i++) {
        float4 v = p[threadIdx.x + i * 256];
        s += (v.x + v.y) + (v.z + v.w);
    }

    __shared__ float sm[256];
    sm[threadIdx.x] = s;
    __syncthreads();
#pragma unroll
    for (int o = 128; o > 0; o >>= 1) {
        if (threadIdx.x < o) sm[threadIdx.x] += sm[threadIdx.x + o];
        __syncthreads();
    }
    if (threadIdx.x == 0) g_pooled[bc] = sm[0] * (1.0f / (float)HW_);
}

// ---------------------------------------------------------------------------
// K2: each block owns 32 float4 spatial columns; loops over all 32 batches.
//     Per batch: weighted channel sum -> xn; accumulates entro (registers),
//     sigmoid partials, and min/max — g_xn buffer and k_entro kernel deleted.
//     512 threads = 32 cols x 16 channel-groups of 16 channels.
// ---------------------------------------------------------------------------
__global__ void __launch_bounds__(512) k_xn(const float* __restrict__ x) {
    const int tid = threadIdx.x;
    const int col = tid & 31;    // float4 column within slice
    const int cg  = tid >> 5;    // 0..15, channel group (16 channels each)
    const int base4 = blockIdx.x * 32;

    __shared__ float  pw[C_];
    __shared__ float4 part[16][32];

    const float4* __restrict__ x4 = reinterpret_cast<const float4*>(x);

    float4 entro_acc = make_float4(0.f, 0.f, 0.f, 0.f);
    float sig = 0.0f;

    for (int b = 0; b < B_; b++) {
        if (tid < C_) pw[tid] = g_pooled[b * C_ + tid];
        __syncthreads();

        const float4* __restrict__ p =
            x4 + ((size_t)b * C_ + cg * 16) * HW4_ + base4 + col;
        float ax = 0.f, ay = 0.f, az = 0.f, aw = 0.f;
#pragma unroll
        for (int ci = 0; ci < 16; ci++) {
            float4 v = p[(size_t)ci * HW4_];
            float w = pw[cg * 16 + ci];
            ax = fmaf(v.x, w, ax);
            ay = fmaf(v.y, w, ay);
            az = fmaf(v.z, w, az);
            aw = fmaf(v.w, w, aw);
        }
        part[cg][col] = make_float4(ax, ay, az, aw);
        __syncthreads();

        if (cg == 0) {   // warp 0
            float4 s = part[0][col];
#pragma unroll
            for (int k = 1; k < 16; k++) {
                float4 t = part[k][col];
                s.x += t.x; s.y += t.y; s.z += t.z; s.w += t.w;
            }
            const float inv = 1.0f / (float)C_;
            s.x *= inv; s.y *= inv; s.z *= inv; s.w *= inv;

            entro_acc.x += s.x; entro_acc.y += s.y;
            entro_acc.z += s.z; entro_acc.w += s.w;

            sig += 1.0f / (1.0f + __expf(-s.x))
                 + 1.0f / (1.0f + __expf(-s.y))
                 + 1.0f / (1.0f + __expf(-s.z))
                 + 1.0f / (1.0f + __expf(-s.w));
        }
        __syncthreads();
    }

    if (cg == 0) {
        const float invB = 1.0f / (float)B_;
        float4 e;
        e.x = entro_acc.x * invB; e.y = entro_acc.y * invB;
        e.z = entro_acc.z * invB; e.w = entro_acc.w * invB;
        reinterpret_cast<float4*>(g_entro)[base4 + col] = e;

        float mn = fminf(fminf(e.x, e.y), fminf(e.z, e.w));
        float mx = fmaxf(fmaxf(e.x, e.y), fmaxf(e.z, e.w));
#pragma unroll
        for (int o = 16; o > 0; o >>= 1) {
            mn  = fminf(mn, __shfl_down_sync(0xffffffffu, mn, o));
            mx  = fmaxf(mx, __shfl_down_sync(0xffffffffu, mx, o));
            sig += __shfl_down_sync(0xffffffffu, sig, o);
        }
        if (col == 0) {
            g_mm[blockIdx.x * 2 + 0] = mn;
            g_mm[blockIdx.x * 2 + 1] = mx;
            g_ssum[blockIdx.x] = sig;
        }
    }
}

// ---------------------------------------------------------------------------
// K3: 64 blocks: reduce the 128 (min,max) pairs (redundant, cheap), bin 256
//     entro elements each into shared histogram, flush to global histogram.
//     Last finished block computes entropy + sigmoid mean + output.
// ---------------------------------------------------------------------------
__global__ void __launch_bounds__(256) k_histout(float* __restrict__ out) {
    const int tid = threadIdx.x;

    __shared__ float smin[128], smax[128];
    __shared__ int hist[256];
    hist[tid] = 0;
    if (tid < 128) {
        smin[tid] = g_mm[tid * 2 + 0];
        smax[tid] = g_mm[tid * 2 + 1];
    }
    __syncthreads();
#pragma unroll
    for (int o = 64; o > 0; o >>= 1) {
        if (tid < o) {
            smin[tid] = fminf(smin[tid], smin[tid + o]);
            smax[tid] = fmaxf(smax[tid], smax[tid + o]);
        }
        __syncthreads();
    }
    const float emin = smin[0];
    const float denom = smax[0] - emin;

    // one element per thread
    float e = (g_entro[blockIdx.x * 256 + tid] - emin) / denom * 255.0f;
    int bin = (int)floorf(e * (256.0f / 255.0f));
    bin = min(max(bin, 0), 255);
    atomicAdd(&hist[bin], 1);
    __syncthreads();

    if (hist[tid] != 0) atomicAdd(&g_hist[tid], hist[tid]);
    __threadfence();

    __shared__ int islast;
    if (tid == 0) islast = (atomicAdd(&g_cnt, 1) == HIST_BLOCKS - 1) ? 1 : 0;
    __syncthreads();
    if (!islast) return;
    __threadfence();

    // --- final: sigmoid-sum reduce (128 partials, deterministic tree)
    __shared__ double sd[128];
    if (tid < 128) sd[tid] = (double)g_ssum[tid];
    __syncthreads();
#pragma unroll
    for (int o = 64; o > 0; o >>= 1) {
        if (tid < o) sd[tid] += sd[tid + o];
        __syncthreads();
    }

    // --- entropy + nonzero count over global histogram
    __shared__ float ssum[256];
    __shared__ int   snz[256];
    int h = __ldcg(&g_hist[tid]);
    float hisv = (float)h * (1.0f / (float)HW_);
    ssum[tid] = hisv * (-logf(hisv + 1e-8f));
    snz[tid]  = (h != 0) ? 1 : 0;
    __syncthreads();
#pragma unroll
    for (int o = 128; o > 0; o >>= 1) {
        if (tid < o) {
            ssum[tid] += ssum[tid + o];
            snz[tid]  += snz[tid + o];
        }
        __syncthreads();
    }

    if (tid == 0) {
        float s = (float)(sd[0] / (double)((size_t)B_ * HW_));
        float entro_final = ssum[0] / (float)snz[0];
        out[0] = s + entro_final * 10.0f;
    }
}

// ---------------------------------------------------------------------------
extern "C" void kernel_launch(void* const* d_in, const int* in_sizes, int n_in,
                              void* d_out, int out_size) {
    const float* x = (const float*)d_in[0];
    float* out = (float*)d_out;

    k_pool<<<B_ * C_, 256>>>(x);
    k_xn<<<XN_BLOCKS, 512>>>(x);
    k_histout<<<HIST_BLOCKS, 256>>>(out);
}

// round 6
// speedup vs baseline: 1.2681x; 1.2681x over previous
#include <cuda_runtime.h>
#include <math_constants.h>

// Shapes (fixed): x: [B=32, C=256, H=128, W=128] float32
#define B_   32
#define C_   256
#define HW_  16384   // 128*128
#define HW4_ 4096    // HW/4 (float4 groups)

#define POOL_BLOCKS 1024   // single wave (<=148*8); 8 channels per block
#define XN_BLOCKS   512    // 32 b * 16 blocks/b (R3 shape)
#define ENTRO_BLOCKS 64
#define HIST_BLOCKS  64

// Scratch (device globals — no allocation allowed)
__device__ float g_pooled[B_ * C_];      // 32 KB
__device__ float g_xn[B_ * HW_];         // 2 MB
__device__ float g_ssum[XN_BLOCKS];      // sigmoid partial per block
__device__ float g_entro[HW_];           // 64 KB
__device__ float g_mm[ENTRO_BLOCKS * 2]; // per-block (min,max)
__device__ int   g_hist[256];
__device__ int   g_cnt;                  // last-block counter

// ---------------------------------------------------------------------------
// K1: pooled[b,c] = mean over HW. Persistent: 1024 blocks x 8 channels each
//     (single wave — removes ~7 wave transitions of the 8192-block version).
//     Block 0 zeroes the histogram + counter for this graph replay.
// ---------------------------------------------------------------------------
__global__ void __launch_bounds__(256) k_pool(const float* __restrict__ x) {
    const int tid = threadIdx.x;
    if (blockIdx.x == 0) {
        g_hist[tid] = 0;
        if (tid == 0) g_cnt = 0;
    }

    __shared__ float sw[8];
    const int lane = tid & 31;
    const int w    = tid >> 5;
    const float4* __restrict__ x4 = reinterpret_cast<const float4*>(x);

#pragma unroll
    for (int it = 0; it < 8; it++) {
        const int bc = it * POOL_BLOCKS + blockIdx.x;   // 0..8191
        const float4* __restrict__ p = x4 + (size_t)bc * HW4_;

        float s = 0.0f;
#pragma unroll
        for (int i = 0; i < 16; i++) {
            float4 v = p[tid + i * 256];
            s += (v.x + v.y) + (v.z + v.w);
        }
        // warp reduce
#pragma unroll
        for (int o = 16; o > 0; o >>= 1)
            s += __shfl_down_sync(0xffffffffu, s, o);
        if (lane == 0) sw[w] = s;
        __syncthreads();
        if (tid == 0) {
            float t = ((sw[0] + sw[1]) + (sw[2] + sw[3]))
                    + ((sw[4] + sw[5]) + (sw[6] + sw[7]));
            g_pooled[bc] = t * (1.0f / (float)HW_);
        }
        __syncthreads();
    }
}

// ---------------------------------------------------------------------------
// K2 (R3 shape): xn[b,sp] = (1/C) * sum_c x[b,c,sp] * pooled[b,c]
//     One thread per float4 spatial group. 16 blocks per batch image.
//     Also per-block sigmoid partials (deterministic tree).
// ---------------------------------------------------------------------------
__global__ void __launch_bounds__(256) k_xn(const float* __restrict__ x) {
    const int b   = blockIdx.x >> 4;                        // 0..31
    const int grp = ((blockIdx.x & 15) << 8) + threadIdx.x; // 0..4095

    __shared__ float pw[C_];
    pw[threadIdx.x] = g_pooled[b * C_ + threadIdx.x];
    __syncthreads();

    const float4* __restrict__ xp =
        reinterpret_cast<const float4*>(x) + (size_t)b * C_ * HW4_ + grp;

    float ax = 0.0f, ay = 0.0f, az = 0.0f, aw = 0.0f;
#pragma unroll 8
    for (int c = 0; c < C_; c++) {
        float4 v = xp[(size_t)c * HW4_];
        float w = pw[c];
        ax = fmaf(v.x, w, ax);
        ay = fmaf(v.y, w, ay);
        az = fmaf(v.z, w, az);
        aw = fmaf(v.w, w, aw);
    }
    const float inv = 1.0f / (float)C_;
    float4 xn;
    xn.x = ax * inv; xn.y = ay * inv; xn.z = az * inv; xn.w = aw * inv;
    reinterpret_cast<float4*>(g_xn)[(size_t)b * HW4_ + grp] = xn;

    float sg = 1.0f / (1.0f + __expf(-xn.x))
             + 1.0f / (1.0f + __expf(-xn.y))
             + 1.0f / (1.0f + __expf(-xn.z))
             + 1.0f / (1.0f + __expf(-xn.w));

    __shared__ float sm[256];
    sm[threadIdx.x] = sg;
    __syncthreads();
#pragma unroll
    for (int o = 128; o > 0; o >>= 1) {
        if (threadIdx.x < o) sm[threadIdx.x] += sm[threadIdx.x + o];
        __syncthreads();
    }
    if (threadIdx.x == 0) g_ssum[blockIdx.x] = sm[0];
}

// ---------------------------------------------------------------------------
// K3: entro[sp] = mean over b of xn[b,sp]; per-block min/max partials.
// ---------------------------------------------------------------------------
__global__ void __launch_bounds__(256) k_entro() {
    const int sp = blockIdx.x * 256 + threadIdx.x;
    float a = 0.0f;
#pragma unroll
    for (int b = 0; b < B_; b++) a += g_xn[(size_t)b * HW_ + sp];
    float v = a * (1.0f / (float)B_);
    g_entro[sp] = v;

    __shared__ float smin[256], smax[256];
    smin[threadIdx.x] = v;
    smax[threadIdx.x] = v;
    __syncthreads();
#pragma unroll
    for (int o = 128; o > 0; o >>= 1) {
        if (threadIdx.x < o) {
            smin[threadIdx.x] = fminf(smin[threadIdx.x], smin[threadIdx.x + o]);
            smax[threadIdx.x] = fmaxf(smax[threadIdx.x], smax[threadIdx.x + o]);
        }
        __syncthreads();
    }
    if (threadIdx.x == 0) {
        g_mm[blockIdx.x * 2 + 0] = smin[0];
        g_mm[blockIdx.x * 2 + 1] = smax[0];
    }
}

// ---------------------------------------------------------------------------
// K4: 64 blocks: reduce min/max partials, bin 256 elements each into shared
//     histogram, flush to global. Last finished block computes the output.
// ---------------------------------------------------------------------------
__global__ void __launch_bounds__(256) k_histout(float* __restrict__ out) {
    const int tid = threadIdx.x;

    __shared__ float smin[64], smax[64];
    __shared__ int hist[256];
    hist[tid] = 0;
    if (tid < 64) {
        smin[tid] = g_mm[tid * 2 + 0];
        smax[tid] = g_mm[tid * 2 + 1];
    }
    __syncthreads();
#pragma unroll
    for (int o = 32; o > 0; o >>= 1) {
        if (tid < o) {
            smin[tid] = fminf(smin[tid], smin[tid + o]);
            smax[tid] = fmaxf(smax[tid], smax[tid + o]);
        }
        __syncthreads();
    }
    const float emin = smin[0];
    const float denom = smax[0] - emin;

    float e = (g_entro[blockIdx.x * 256 + tid] - emin) / denom * 255.0f;
    int bin = (int)floorf(e * (256.0f / 255.0f));
    bin = min(max(bin, 0), 255);
    atomicAdd(&hist[bin], 1);
    __syncthreads();

    if (hist[tid] != 0) atomicAdd(&g_hist[tid], hist[tid]);
    __threadfence();

    __shared__ int islast;
    if (tid == 0) islast = (atomicAdd(&g_cnt, 1) == HIST_BLOCKS - 1) ? 1 : 0;
    __syncthreads();
    if (!islast) return;
    __threadfence();

    // sigmoid-sum reduce (512 partials, deterministic tree)
    __shared__ double sd[256];
    sd[tid] = (double)g_ssum[tid] + (double)g_ssum[tid + 256];
    __syncthreads();
#pragma unroll
    for (int o = 128; o > 0; o >>= 1) {
        if (tid < o) sd[tid] += sd[tid + o];
        __syncthreads();
    }

    // entropy + nonzero count over global histogram
    __shared__ float ssum[256];
    __shared__ int   snz[256];
    int h = __ldcg(&g_hist[tid]);
    float hisv = (float)h * (1.0f / (float)HW_);
    ssum[tid] = hisv * (-logf(hisv + 1e-8f));
    snz[tid]  = (h != 0) ? 1 : 0;
    __syncthreads();
#pragma unroll
    for (int o = 128; o > 0; o >>= 1) {
        if (tid < o) {
            ssum[tid] += ssum[tid + o];
            snz[tid]  += snz[tid + o];
        }
        __syncthreads();
    }

    if (tid == 0) {
        float s = (float)(sd[0] / (double)((size_t)B_ * HW_));
        float entro_final = ssum[0] / (float)snz[0];
        out[0] = s + entro_final * 10.0f;
    }
}

// ---------------------------------------------------------------------------
extern "C" void kernel_launch(void* const* d_in, const int* in_sizes, int n_in,
                              void* d_out, int out_size) {
    const float* x = (const float*)d_in[0];
    float* out = (float*)d_out;

    k_pool<<<POOL_BLOCKS, 256>>>(x);
    k_xn<<<XN_BLOCKS, 256>>>(x);
    k_entro<<<ENTRO_BLOCKS, 256>>>();
    k_histout<<<HIST_BLOCKS, 256>>>(out);
}